// round 14
// baseline (speedup 1.0000x reference)
#include <cuda_runtime.h>
#include <cuda_bf16.h>
#include <cstdint>

// Problem constants
#define BB      4
#define NN      10000
#define EE      160000
#define HH      128
#define NHEADS  4
#define HOUT    512      // NHEADS * HH
#define MTOT    (BB*NN)  // 40000 rows

// ---------------------------------------------------------------------------
// Static device scratch
// ---------------------------------------------------------------------------
__device__ __nv_bfloat16 d_Agghi[(size_t)BB * NN * HOUT]; // aggregated X, bf16 hi
__device__ __nv_bfloat16 d_Agglo[(size_t)BB * NN * HOUT]; // aggregated X, bf16 lo
__device__ float d_X[(size_t)BB * NN * HH];         // layer activations  [B*N, 128]
__device__ float d_esrc[BB * NN * NHEADS];
__device__ float d_edst[BB * NN * NHEADS];
__device__ int   d_cnt[BB * (NN + 1)];
__device__ int   d_off[BB * (NN + 1)];
__device__ int   d_cur[BB * NN];
__device__ int   d_es [BB * EE];
__device__ float d_Ws[HH * NHEADS];
__device__ float d_Wd[HH * NHEADS];
__device__ __nv_bfloat16 d_WThi[HH * HOUT];         // W^T split, [c=128][k=512], 0.25 folded
__device__ __nv_bfloat16 d_WTlo[HH * HOUT];

__device__ __forceinline__ float lrelu(float x) { return x > 0.f ? x : 0.2f * x; }

__device__ __forceinline__ uint32_t s2u(const void* p) {
    return (uint32_t)__cvta_generic_to_shared(p);
}
__device__ __forceinline__ uint32_t packbf(float x, float y) {
    __nv_bfloat162 t = __floats2bfloat162_rn(x, y);
    return *(uint32_t*)&t;
}
__device__ __forceinline__ void ldsm4(uint32_t* r, uint32_t addr) {
    asm volatile("ldmatrix.sync.aligned.m8n8.x4.shared.b16 {%0,%1,%2,%3}, [%4];\n"
                 : "=r"(r[0]), "=r"(r[1]), "=r"(r[2]), "=r"(r[3]) : "r"(addr));
}
__device__ __forceinline__ void mma16816(float* c, const uint32_t* a, const uint32_t* b) {
    asm volatile("mma.sync.aligned.m16n8k16.row.col.f32.bf16.bf16.f32 "
                 "{%0,%1,%2,%3}, {%4,%5,%6,%7}, {%8,%9}, {%0,%1,%2,%3};\n"
                 : "+f"(c[0]), "+f"(c[1]), "+f"(c[2]), "+f"(c[3])
                 : "r"(a[0]), "r"(a[1]), "r"(a[2]), "r"(a[3]), "r"(b[0]), "r"(b[1]));
}

// ---------------------------------------------------------------------------
// CSR build
// ---------------------------------------------------------------------------
__global__ void k_zero_cnt() {
    int i = blockIdx.x * blockDim.x + threadIdx.x;
    if (i < BB * (NN + 1)) d_cnt[i] = 0;
}
__global__ void k_hist(const int* __restrict__ tgt) {
    int e = blockIdx.x * blockDim.x + threadIdx.x;
    if (e < BB * EE) {
        int b = e / EE;
        atomicAdd(&d_cnt[b * (NN + 1) + tgt[e]], 1);
    }
}
__global__ void k_scan() {
    int b = blockIdx.x;
    __shared__ int sh[1024];
    __shared__ int s_run;
    int tid = threadIdx.x;
    if (tid == 0) s_run = 0;
    __syncthreads();
    for (int base = 0; base < NN; base += 1024) {
        int idx = base + tid;
        int c = (idx < NN) ? d_cnt[b * (NN + 1) + idx] : 0;
        sh[tid] = c;
        __syncthreads();
        #pragma unroll
        for (int st = 1; st < 1024; st <<= 1) {
            int v = (tid >= st) ? sh[tid - st] : 0;
            __syncthreads();
            sh[tid] += v;
            __syncthreads();
        }
        int run = s_run;
        if (idx < NN) {
            int excl = run + sh[tid] - c;
            d_off[b * (NN + 1) + idx] = excl;
            d_cur[b * NN + idx]       = excl;
        }
        __syncthreads();
        if (tid == 1023) s_run = run + sh[1023];
        __syncthreads();
    }
    if (tid == 0) d_off[b * (NN + 1) + NN] = s_run;
}
__global__ void k_scatter(const int* __restrict__ src, const int* __restrict__ tgt) {
    int e = blockIdx.x * blockDim.x + threadIdx.x;
    if (e < BB * EE) {
        int b = e / EE;
        int t = tgt[e];
        int p = atomicAdd(&d_cur[b * NN + t], 1);
        d_es[(size_t)b * EE + p] = src[e];
    }
}

// ---------------------------------------------------------------------------
// Merged per-layer prep:
//  blocks 0..15  : bf16 split of 0.25*W^T
//  blocks 16..19 : attention projection vectors
// ---------------------------------------------------------------------------
__global__ void __launch_bounds__(256) k_prep(const float* __restrict__ W,
                                              const float* __restrict__ as_,
                                              const float* __restrict__ ad_) {
    int blk = blockIdx.x;
    int t = threadIdx.x;
    if (blk < 16) {
        int c = blk * 8 + (t >> 5);
        int kb = (t & 31) * 16;
        __nv_bfloat16 hi[16], lo[16];
        #pragma unroll
        for (int i = 0; i < 16; i++) {
            int k = kb + i;
            float val = 0.25f * W[(size_t)(k & 127) * HOUT + (k >> 7) * HH + c];
            __nv_bfloat16 h = __float2bfloat16_rn(val);
            hi[i] = h;
            lo[i] = __float2bfloat16_rn(val - __bfloat162float(h));
        }
        size_t base = (size_t)c * HOUT + kb;
        *(uint4*)&d_WThi[base]     = *(uint4*)&hi[0];
        *(uint4*)&d_WThi[base + 8] = *(uint4*)&hi[8];
        *(uint4*)&d_WTlo[base]     = *(uint4*)&lo[0];
        *(uint4*)&d_WTlo[base + 8] = *(uint4*)&lo[8];
    } else {
        int tt = (blk - 16) * 256 + t;       // 0..1023
        int c = tt >> 3;
        int q = tt & 7;
        int h = q & 3;
        bool is_d = (q >= 4);
        const float* a = is_d ? ad_ : as_;
        float sum = 0.f;
        const float* wr = W + (size_t)c * HOUT + h * HH;
        const float* ar = a + h * HH;
        #pragma unroll 8
        for (int k = 0; k < HH; k++) sum = fmaf(wr[k], ar[k], sum);
        if (is_d) d_Wd[c * NHEADS + h] = sum;
        else      d_Ws[c * NHEADS + h] = sum;
    }
}

// ---------------------------------------------------------------------------
// escore: warp per row
// ---------------------------------------------------------------------------
__global__ void __launch_bounds__(256) k_escore(const float* __restrict__ Xin) {
    __shared__ float sWs[HH * NHEADS];
    __shared__ float sWd[HH * NHEADS];
    int tid = threadIdx.x;
    sWs[tid] = d_Ws[tid]; sWs[tid + 256] = d_Ws[tid + 256];
    sWd[tid] = d_Wd[tid]; sWd[tid + 256] = d_Wd[tid + 256];
    __syncthreads();

    int row = blockIdx.x * 8 + (tid >> 5);
    int lane = tid & 31;
    float4 x = *(const float4*)&Xin[(size_t)row * HH + lane * 4];
    float xv[4] = {x.x, x.y, x.z, x.w};
    float p[8] = {0, 0, 0, 0, 0, 0, 0, 0};
    #pragma unroll
    for (int i = 0; i < 4; i++) {
        int c = lane * 4 + i;
        #pragma unroll
        for (int h = 0; h < 4; h++) {
            p[h]     = fmaf(xv[i], sWs[c * 4 + h], p[h]);
            p[4 + h] = fmaf(xv[i], sWd[c * 4 + h], p[4 + h]);
        }
    }
    #pragma unroll
    for (int s = 16; s > 0; s >>= 1) {
        #pragma unroll
        for (int q = 0; q < 8; q++)
            p[q] += __shfl_xor_sync(0xffffffffu, p[q], s);
    }
    if (lane == 0) {
        *(float4*)&d_esrc[row * 4] = make_float4(p[0], p[1], p[2], p[3]);
        *(float4*)&d_edst[row * 4] = make_float4(p[4], p[5], p[6], p[7]);
    }
}

// ---------------------------------------------------------------------------
// Fused attention + gather: WARP per node (8 nodes / 256-thread block).
// Sweep 1: per-head max over edges.
// Sweep 2: per-lane exp of own edge (chunk of 32) -> shuffle-broadcast
//          (src, ex[4]) -> all lanes accumulate alpha-weighted X.
// Epilogue: add self term, scale by 1/(sum+ex_self), write bf16 hi/lo split.
// No d_alpha tensor, 2 edge sweeps instead of 4.
// ---------------------------------------------------------------------------
__global__ void __launch_bounds__(256) k_attgather(const float* __restrict__ Xin) {
    const int w = blockIdx.x * 8 + (threadIdx.x >> 5);   // node id
    const int lane = threadIdx.x & 31;
    const int b = w / NN;
    const int n = w - b * NN;
    const int beg = d_off[b * (NN + 1) + n];
    const int cnte = d_off[b * (NN + 1) + n + 1] - beg;
    const size_t ebase = (size_t)b * EE + beg;
    const float* Xb = Xin + (size_t)b * NN * HH;

    float4 ed4 = __ldg((const float4*)&d_edst[w * 4]);
    float edv[4] = {ed4.x, ed4.y, ed4.z, ed4.w};
    float4 es4 = __ldg((const float4*)&d_esrc[w * 4]);
    float e_self[4] = {lrelu(es4.x + edv[0]), lrelu(es4.y + edv[1]),
                       lrelu(es4.z + edv[2]), lrelu(es4.w + edv[3])};

    // ---- sweep 1: per-head max ----
    float mx[4] = {e_self[0], e_self[1], e_self[2], e_self[3]};
    for (int j = lane; j < cnte; j += 32) {
        int src = __ldg(&d_es[ebase + j]);
        float4 e4 = __ldg((const float4*)&d_esrc[((size_t)b * NN + src) * 4]);
        mx[0] = fmaxf(mx[0], lrelu(e4.x + edv[0]));
        mx[1] = fmaxf(mx[1], lrelu(e4.y + edv[1]));
        mx[2] = fmaxf(mx[2], lrelu(e4.z + edv[2]));
        mx[3] = fmaxf(mx[3], lrelu(e4.w + edv[3]));
    }
    #pragma unroll
    for (int s = 16; s > 0; s >>= 1)
        #pragma unroll
        for (int h = 0; h < 4; h++) mx[h] = fmaxf(mx[h], __shfl_xor_sync(0xffffffffu, mx[h], s));

    // ---- sweep 2: fused exp + gather ----
    float4 a0 = make_float4(0, 0, 0, 0);
    float4 a1 = make_float4(0, 0, 0, 0);
    float4 a2 = make_float4(0, 0, 0, 0);
    float4 a3 = make_float4(0, 0, 0, 0);
    float sm[4] = {0, 0, 0, 0};

    for (int cb = 0; cb < cnte; cb += 32) {
        int m = min(32, cnte - cb);
        int msrc = 0;
        float ex0 = 0.f, ex1 = 0.f, ex2 = 0.f, ex3 = 0.f;
        if (lane < m) {
            msrc = __ldg(&d_es[ebase + cb + lane]);
            float4 e4 = __ldg((const float4*)&d_esrc[((size_t)b * NN + msrc) * 4]);
            ex0 = __expf(lrelu(e4.x + edv[0]) - mx[0]);
            ex1 = __expf(lrelu(e4.y + edv[1]) - mx[1]);
            ex2 = __expf(lrelu(e4.z + edv[2]) - mx[2]);
            ex3 = __expf(lrelu(e4.w + edv[3]) - mx[3]);
            sm[0] += ex0; sm[1] += ex1; sm[2] += ex2; sm[3] += ex3;
        }
        for (int j = 0; j < m; j++) {
            int s = __shfl_sync(0xffffffffu, msrc, j);
            float alx = __shfl_sync(0xffffffffu, ex0, j);
            float aly = __shfl_sync(0xffffffffu, ex1, j);
            float alz = __shfl_sync(0xffffffffu, ex2, j);
            float alw = __shfl_sync(0xffffffffu, ex3, j);
            float4 x = __ldg((const float4*)&Xb[(size_t)s * HH + lane * 4]);
            a0.x = fmaf(alx, x.x, a0.x); a0.y = fmaf(alx, x.y, a0.y);
            a0.z = fmaf(alx, x.z, a0.z); a0.w = fmaf(alx, x.w, a0.w);
            a1.x = fmaf(aly, x.x, a1.x); a1.y = fmaf(aly, x.y, a1.y);
            a1.z = fmaf(aly, x.z, a1.z); a1.w = fmaf(aly, x.w, a1.w);
            a2.x = fmaf(alz, x.x, a2.x); a2.y = fmaf(alz, x.y, a2.y);
            a2.z = fmaf(alz, x.z, a2.z); a2.w = fmaf(alz, x.w, a2.w);
            a3.x = fmaf(alw, x.x, a3.x); a3.y = fmaf(alw, x.y, a3.y);
            a3.z = fmaf(alw, x.z, a3.z); a3.w = fmaf(alw, x.w, a3.w);
        }
    }
    // reduce sums across lanes
    #pragma unroll
    for (int s = 16; s > 0; s >>= 1)
        #pragma unroll
        for (int h = 0; h < 4; h++) sm[h] += __shfl_xor_sync(0xffffffffu, sm[h], s);

    // ---- epilogue: self term + normalize ----
    float ex_self[4], inv[4];
    #pragma unroll
    for (int h = 0; h < 4; h++) {
        ex_self[h] = __expf(e_self[h] - mx[h]);
        inv[h] = 1.f / (sm[h] + ex_self[h]);
    }
    float4 xs = __ldg((const float4*)&Xb[(size_t)n * HH + lane * 4]);

    a0.x = (a0.x + ex_self[0] * xs.x) * inv[0];
    a0.y = (a0.y + ex_self[0] * xs.y) * inv[0];
    a0.z = (a0.z + ex_self[0] * xs.z) * inv[0];
    a0.w = (a0.w + ex_self[0] * xs.w) * inv[0];
    a1.x = (a1.x + ex_self[1] * xs.x) * inv[1];
    a1.y = (a1.y + ex_self[1] * xs.y) * inv[1];
    a1.z = (a1.z + ex_self[1] * xs.z) * inv[1];
    a1.w = (a1.w + ex_self[1] * xs.w) * inv[1];
    a2.x = (a2.x + ex_self[2] * xs.x) * inv[2];
    a2.y = (a2.y + ex_self[2] * xs.y) * inv[2];
    a2.z = (a2.z + ex_self[2] * xs.z) * inv[2];
    a2.w = (a2.w + ex_self[2] * xs.w) * inv[2];
    a3.x = (a3.x + ex_self[3] * xs.x) * inv[3];
    a3.y = (a3.y + ex_self[3] * xs.y) * inv[3];
    a3.z = (a3.z + ex_self[3] * xs.z) * inv[3];
    a3.w = (a3.w + ex_self[3] * xs.w) * inv[3];

    // bf16 hi/lo split write, per head
    size_t obase = (size_t)w * HOUT + lane * 4;
    float4 acc[4] = {a0, a1, a2, a3};
    #pragma unroll
    for (int h = 0; h < 4; h++) {
        float4 r = acc[h];
        float hx = __bfloat162float(__float2bfloat16_rn(r.x));
        float hy = __bfloat162float(__float2bfloat16_rn(r.y));
        float hz = __bfloat162float(__float2bfloat16_rn(r.z));
        float hw = __bfloat162float(__float2bfloat16_rn(r.w));
        uint32_t hi01 = packbf(r.x, r.y);
        uint32_t hi23 = packbf(r.z, r.w);
        uint32_t lo01 = packbf(r.x - hx, r.y - hy);
        uint32_t lo23 = packbf(r.z - hz, r.w - hw);
        *(uint2*)&d_Agghi[obase + h * HH] = make_uint2(hi01, hi23);
        *(uint2*)&d_Agglo[obase + h * HH] = make_uint2(lo01, lo23);
    }
}

// ---------------------------------------------------------------------------
// Tensor-core GEMM + fused epilogue. A is pre-split bf16 (no convert in loop).
// BM=128, BN=128, BK=32, 256 threads, 8 warps as 4(M)x2(N).
// ---------------------------------------------------------------------------
#define SPAD 40
__global__ void __launch_bounds__(256) k_gemm_tc(const float* __restrict__ bias,
                                                 const float* __restrict__ g,
                                                 const float* __restrict__ bparm,
                                                 float* __restrict__ outp,
                                                 int mode) {
    __shared__ __nv_bfloat16 sAhi[128 * SPAD];
    __shared__ __nv_bfloat16 sAlo[128 * SPAD];
    __shared__ __nv_bfloat16 sBhi[128 * SPAD];
    __shared__ __nv_bfloat16 sBlo[128 * SPAD];
    __shared__ float sred[2][2][128];

    const int tid  = threadIdx.x;
    const int lane = tid & 31;
    const int wid  = tid >> 5;
    const int wm   = wid & 3;
    const int wn   = wid >> 2;
    const int brow = blockIdx.x * 128;

    const int lr = tid >> 1;
    const int lk = (tid & 1) * 16;
    const int grow = brow + lr;
    const bool arow_ok = (grow < MTOT);

    float c[2][8][4];
    #pragma unroll
    for (int i = 0; i < 2; i++)
        #pragma unroll
        for (int j = 0; j < 8; j++)
            #pragma unroll
            for (int q = 0; q < 4; q++) c[i][j][q] = 0.f;

    const uint32_t uAhi = s2u(sAhi), uAlo = s2u(sAlo);
    const uint32_t uBhi = s2u(sBhi), uBlo = s2u(sBlo);

    uint4 ah0, ah1, al0, al1;
    uint4 bh0, bh1, bl0, bl1;
    const uint4 z4 = make_uint4(0, 0, 0, 0);

    {
        if (arow_ok) {
            const uint4* pah = (const uint4*)&d_Agghi[(size_t)grow * HOUT + lk];
            const uint4* pal = (const uint4*)&d_Agglo[(size_t)grow * HOUT + lk];
            ah0 = pah[0]; ah1 = pah[1];
            al0 = pal[0]; al1 = pal[1];
        } else {
            ah0 = ah1 = al0 = al1 = z4;
        }
        const uint4* pbh = (const uint4*)&d_WThi[(size_t)lr * HOUT + lk];
        const uint4* pbl = (const uint4*)&d_WTlo[(size_t)lr * HOUT + lk];
        bh0 = pbh[0]; bh1 = pbh[1];
        bl0 = pbl[0]; bl1 = pbl[1];
    }

    #pragma unroll 1
    for (int it = 0; it < HOUT / 32; it++) {
        {
            int so = lr * SPAD + lk;
            *(uint4*)&sAhi[so]     = ah0;
            *(uint4*)&sAhi[so + 8] = ah1;
            *(uint4*)&sAlo[so]     = al0;
            *(uint4*)&sAlo[so + 8] = al1;
            *(uint4*)&sBhi[so]     = bh0;
            *(uint4*)&sBhi[so + 8] = bh1;
            *(uint4*)&sBlo[so]     = bl0;
            *(uint4*)&sBlo[so + 8] = bl1;
        }
        __syncthreads();

        if (it + 1 < HOUT / 32) {
            int k0 = (it + 1) * 32;
            if (arow_ok) {
                const uint4* pah = (const uint4*)&d_Agghi[(size_t)grow * HOUT + k0 + lk];
                const uint4* pal = (const uint4*)&d_Agglo[(size_t)grow * HOUT + k0 + lk];
                ah0 = pah[0]; ah1 = pah[1];
                al0 = pal[0]; al1 = pal[1];
            }
            const uint4* pbh = (const uint4*)&d_WThi[(size_t)lr * HOUT + k0 + lk];
            const uint4* pbl = (const uint4*)&d_WTlo[(size_t)lr * HOUT + k0 + lk];
            bh0 = pbh[0]; bh1 = pbh[1];
            bl0 = pbl[0]; bl1 = pbl[1];
        }

        #pragma unroll
        for (int ks = 0; ks < 2; ks++) {
            const int kk = ks * 16;
            uint32_t ahi[2][4], alo[2][4];
            #pragma unroll
            for (int mt = 0; mt < 2; mt++) {
                int rb = wm * 32 + mt * 16;
                uint32_t off = 2u * ((rb + (lane & 15)) * SPAD + kk + (lane >> 4) * 8);
                ldsm4(ahi[mt], uAhi + off);
                ldsm4(alo[mt], uAlo + off);
            }
            #pragma unroll
            for (int np = 0; np < 4; np++) {
                int cb = wn * 64 + np * 16;
                uint32_t boff = 2u * ((cb + (lane >> 4) * 8 + (lane & 7)) * SPAD
                                      + kk + ((lane >> 3) & 1) * 8);
                uint32_t bh[4], bl[4];
                ldsm4(bh, uBhi + boff);
                ldsm4(bl, uBlo + boff);
                #pragma unroll
                for (int half = 0; half < 2; half++) {
                    int nt = np * 2 + half;
                    #pragma unroll
                    for (int mt = 0; mt < 2; mt++) {
                        mma16816(c[mt][nt], ahi[mt], &bh[half * 2]);
                        mma16816(c[mt][nt], ahi[mt], &bl[half * 2]);
                        mma16816(c[mt][nt], alo[mt], &bh[half * 2]);
                    }
                }
            }
        }
        __syncthreads();
    }

    // ---- fused epilogue ----
    const int colq = (lane & 3) * 2;

    #pragma unroll
    for (int nt = 0; nt < 8; nt++) {
        int col = wn * 64 + nt * 8 + colq;
        float b0 = __ldg(&bias[col]);
        float b1 = __ldg(&bias[col + 1]);
        #pragma unroll
        for (int mt = 0; mt < 2; mt++) {
            c[mt][nt][0] += b0; c[mt][nt][1] += b1;
            c[mt][nt][2] += b0; c[mt][nt][3] += b1;
        }
    }

    if (mode == 1) {
        #pragma unroll
        for (int mt = 0; mt < 2; mt++) {
            #pragma unroll
            for (int nt = 0; nt < 8; nt++) {
                int r0 = brow + wm * 32 + mt * 16 + (lane >> 2);
                int col = wn * 64 + nt * 8 + colq;
                if (r0 < MTOT)
                    *(float2*)&outp[(size_t)r0 * HH + col] = make_float2(c[mt][nt][0], c[mt][nt][1]);
                if (r0 + 8 < MTOT)
                    *(float2*)&outp[(size_t)(r0 + 8) * HH + col] = make_float2(c[mt][nt][2], c[mt][nt][3]);
            }
        }
        return;
    }

    // mean
    #pragma unroll
    for (int mt = 0; mt < 2; mt++) {
        float p0 = 0.f, p1 = 0.f;
        #pragma unroll
        for (int nt = 0; nt < 8; nt++) {
            p0 += c[mt][nt][0] + c[mt][nt][1];
            p1 += c[mt][nt][2] + c[mt][nt][3];
        }
        p0 += __shfl_xor_sync(0xffffffffu, p0, 1);
        p0 += __shfl_xor_sync(0xffffffffu, p0, 2);
        p1 += __shfl_xor_sync(0xffffffffu, p1, 1);
        p1 += __shfl_xor_sync(0xffffffffu, p1, 2);
        if ((lane & 3) == 0) {
            int r = wm * 32 + mt * 16 + (lane >> 2);
            sred[0][wn][r]     = p0;
            sred[0][wn][r + 8] = p1;
        }
    }
    __syncthreads();
    float mu[2][2];
    #pragma unroll
    for (int mt = 0; mt < 2; mt++) {
        int r = wm * 32 + mt * 16 + (lane >> 2);
        mu[mt][0] = (sred[0][0][r]     + sred[0][1][r])     * (1.f / 128.f);
        mu[mt][1] = (sred[0][0][r + 8] + sred[0][1][r + 8]) * (1.f / 128.f);
    }

    // variance
    #pragma unroll
    for (int mt = 0; mt < 2; mt++) {
        float p0 = 0.f, p1 = 0.f;
        #pragma unroll
        for (int nt = 0; nt < 8; nt++) {
            float d0 = c[mt][nt][0] - mu[mt][0];
            float d1 = c[mt][nt][1] - mu[mt][0];
            float d2 = c[mt][nt][2] - mu[mt][1];
            float d3 = c[mt][nt][3] - mu[mt][1];
            p0 += d0 * d0 + d1 * d1;
            p1 += d2 * d2 + d3 * d3;
        }
        p0 += __shfl_xor_sync(0xffffffffu, p0, 1);
        p0 += __shfl_xor_sync(0xffffffffu, p0, 2);
        p1 += __shfl_xor_sync(0xffffffffu, p1, 1);
        p1 += __shfl_xor_sync(0xffffffffu, p1, 2);
        if ((lane & 3) == 0) {
            int r = wm * 32 + mt * 16 + (lane >> 2);
            sred[1][wn][r]     = p0;
            sred[1][wn][r + 8] = p1;
        }
    }
    __syncthreads();
    float rst[2][2];
    #pragma unroll
    for (int mt = 0; mt < 2; mt++) {
        int r = wm * 32 + mt * 16 + (lane >> 2);
        rst[mt][0] = rsqrtf((sred[1][0][r]     + sred[1][1][r])     * (1.f / 128.f) + 1e-5f);
        rst[mt][1] = rsqrtf((sred[1][0][r + 8] + sred[1][1][r + 8]) * (1.f / 128.f) + 1e-5f);
    }

    // normalize + ReLU + store
    #pragma unroll
    for (int nt = 0; nt < 8; nt++) {
        int col = wn * 64 + nt * 8 + colq;
        float g0 = __ldg(&g[col]),      g1 = __ldg(&g[col + 1]);
        float q0 = __ldg(&bparm[col]),  q1 = __ldg(&bparm[col + 1]);
        #pragma unroll
        for (int mt = 0; mt < 2; mt++) {
            int r0 = brow + wm * 32 + mt * 16 + (lane >> 2);
            if (r0 < MTOT) {
                float o0 = fmaxf(fmaf((c[mt][nt][0] - mu[mt][0]) * rst[mt][0], g0, q0), 0.f);
                float o1 = fmaxf(fmaf((c[mt][nt][1] - mu[mt][0]) * rst[mt][0], g1, q1), 0.f);
                *(float2*)&d_X[(size_t)r0 * HH + col] = make_float2(o0, o1);
            }
            if (r0 + 8 < MTOT) {
                float o2 = fmaxf(fmaf((c[mt][nt][2] - mu[mt][1]) * rst[mt][1], g0, q0), 0.f);
                float o3 = fmaxf(fmaf((c[mt][nt][3] - mu[mt][1]) * rst[mt][1], g1, q1), 0.f);
                *(float2*)&d_X[(size_t)(r0 + 8) * HH + col] = make_float2(o2, o3);
            }
        }
    }
}

// ---------------------------------------------------------------------------
// Launch
// ---------------------------------------------------------------------------
extern "C" void kernel_launch(void* const* d_in, const int* in_sizes, int n_in,
                              void* d_out, int out_size) {
    const float* x0   = (const float*)d_in[0];
    const int*   src  = (const int*)d_in[1];
    const int*   tgt  = (const int*)d_in[2];
    const float* W1   = (const float*)d_in[3];
    const float* as1  = (const float*)d_in[4];
    const float* ad1  = (const float*)d_in[5];
    const float* b1   = (const float*)d_in[6];
    const float* W2   = (const float*)d_in[7];
    const float* as2  = (const float*)d_in[8];
    const float* ad2  = (const float*)d_in[9];
    const float* b2   = (const float*)d_in[10];
    const float* W3   = (const float*)d_in[11];
    const float* as3  = (const float*)d_in[12];
    const float* ad3  = (const float*)d_in[13];
    const float* b3   = (const float*)d_in[14];
    const float* g1   = (const float*)d_in[15];
    const float* bb1  = (const float*)d_in[16];
    const float* g2   = (const float*)d_in[17];
    const float* bb2  = (const float*)d_in[18];
    float* out = (float*)d_out;

    float* d_X_ptr;
    cudaGetSymbolAddress((void**)&d_X_ptr, d_X);

    // ---- CSR build ----
    k_zero_cnt<<<(BB * (NN + 1) + 255) / 256, 256>>>();
    k_hist<<<(BB * EE + 255) / 256, 256>>>(tgt);
    k_scan<<<BB, 1024>>>();
    k_scatter<<<(BB * EE + 255) / 256, 256>>>(src, tgt);

    const int gw = MTOT / 8;             // warp-per-node grids (5000)
    const int gm = (MTOT + 127) / 128;

    // ---- Layer 1 ----
    k_prep<<<20, 256>>>(W1, as1, ad1);
    k_escore<<<gw, 256>>>(x0);
    k_attgather<<<gw, 256>>>(x0);
    k_gemm_tc<<<gm, 256>>>(b1, g1, bb1, nullptr, 0);

    // ---- Layer 2 ----
    k_prep<<<20, 256>>>(W2, as2, ad2);
    k_escore<<<gw, 256>>>(d_X_ptr);
    k_attgather<<<gw, 256>>>(d_X_ptr);
    k_gemm_tc<<<gm, 256>>>(b2, g2, bb2, nullptr, 0);

    // ---- Layer 3 ----
    k_prep<<<20, 256>>>(W3, as3, ad3);
    k_escore<<<gw, 256>>>(d_X_ptr);
    k_attgather<<<gw, 256>>>(d_X_ptr);
    k_gemm_tc<<<gm, 256>>>(b3, nullptr, nullptr, out, 1);
}

// round 15
// speedup vs baseline: 1.0807x; 1.0807x over previous
#include <cuda_runtime.h>
#include <cuda_bf16.h>
#include <cstdint>

// Problem constants
#define BB      4
#define NN      10000
#define EE      160000
#define HH      128
#define NHEADS  4
#define HOUT    512      // NHEADS * HH
#define MTOT    (BB*NN)  // 40000 rows

// ---------------------------------------------------------------------------
// Static device scratch
// ---------------------------------------------------------------------------
__device__ __nv_bfloat16 d_Agghi[(size_t)BB * NN * HOUT]; // aggregated X, bf16 hi
__device__ __nv_bfloat16 d_Agglo[(size_t)BB * NN * HOUT]; // aggregated X, bf16 lo
__device__ float d_X[(size_t)BB * NN * HH];         // layer activations  [B*N, 128]
__device__ float d_esrc[BB * NN * NHEADS];
__device__ float d_edst[BB * NN * NHEADS];
__device__ float d_alpha[(size_t)BB * EE * NHEADS]; // UNNORMALIZED exp weights
__device__ float d_aself[BB * NN * NHEADS];         // unnormalized self exp
__device__ float d_ainv[BB * NN * NHEADS];          // per-node 1/sum
__device__ unsigned d_gmax[BB * NHEADS];            // encoded global max of esrc
__device__ int   d_cnt[BB * (NN + 1)];
__device__ int   d_off[BB * (NN + 1)];
__device__ int   d_cur[BB * NN];
__device__ int   d_es [BB * EE];
__device__ float d_Ws[HH * NHEADS];
__device__ float d_Wd[HH * NHEADS];
__device__ __nv_bfloat16 d_WThi[HH * HOUT];         // W^T split, [c=128][k=512], 0.25 folded
__device__ __nv_bfloat16 d_WTlo[HH * HOUT];

__device__ __forceinline__ float lrelu(float x) { return x > 0.f ? x : 0.2f * x; }

// monotone float<->uint encoding for atomicMax on floats (any sign)
__device__ __forceinline__ unsigned encf(float f) {
    unsigned u = __float_as_uint(f);
    return (u & 0x80000000u) ? ~u : (u | 0x80000000u);
}
__device__ __forceinline__ float decf(unsigned e) {
    return (e & 0x80000000u) ? __uint_as_float(e & 0x7fffffffu) : __uint_as_float(~e);
}

__device__ __forceinline__ uint32_t s2u(const void* p) {
    return (uint32_t)__cvta_generic_to_shared(p);
}
__device__ __forceinline__ uint32_t packbf(float x, float y) {
    __nv_bfloat162 t = __floats2bfloat162_rn(x, y);
    return *(uint32_t*)&t;
}
__device__ __forceinline__ void ldsm4(uint32_t* r, uint32_t addr) {
    asm volatile("ldmatrix.sync.aligned.m8n8.x4.shared.b16 {%0,%1,%2,%3}, [%4];\n"
                 : "=r"(r[0]), "=r"(r[1]), "=r"(r[2]), "=r"(r[3]) : "r"(addr));
}
__device__ __forceinline__ void mma16816(float* c, const uint32_t* a, const uint32_t* b) {
    asm volatile("mma.sync.aligned.m16n8k16.row.col.f32.bf16.bf16.f32 "
                 "{%0,%1,%2,%3}, {%4,%5,%6,%7}, {%8,%9}, {%0,%1,%2,%3};\n"
                 : "+f"(c[0]), "+f"(c[1]), "+f"(c[2]), "+f"(c[3])
                 : "r"(a[0]), "r"(a[1]), "r"(a[2]), "r"(a[3]), "r"(b[0]), "r"(b[1]));
}

// ---------------------------------------------------------------------------
// CSR build
// ---------------------------------------------------------------------------
__global__ void k_zero_cnt() {
    int i = blockIdx.x * blockDim.x + threadIdx.x;
    if (i < BB * (NN + 1)) d_cnt[i] = 0;
}
__global__ void k_hist(const int* __restrict__ tgt) {
    int e = blockIdx.x * blockDim.x + threadIdx.x;
    if (e < BB * EE) {
        int b = e / EE;
        atomicAdd(&d_cnt[b * (NN + 1) + tgt[e]], 1);
    }
}
__global__ void k_scan() {
    int b = blockIdx.x;
    __shared__ int sh[1024];
    __shared__ int s_run;
    int tid = threadIdx.x;
    if (tid == 0) s_run = 0;
    __syncthreads();
    for (int base = 0; base < NN; base += 1024) {
        int idx = base + tid;
        int c = (idx < NN) ? d_cnt[b * (NN + 1) + idx] : 0;
        sh[tid] = c;
        __syncthreads();
        #pragma unroll
        for (int st = 1; st < 1024; st <<= 1) {
            int v = (tid >= st) ? sh[tid - st] : 0;
            __syncthreads();
            sh[tid] += v;
            __syncthreads();
        }
        int run = s_run;
        if (idx < NN) {
            int excl = run + sh[tid] - c;
            d_off[b * (NN + 1) + idx] = excl;
            d_cur[b * NN + idx]       = excl;
        }
        __syncthreads();
        if (tid == 1023) s_run = run + sh[1023];
        __syncthreads();
    }
    if (tid == 0) d_off[b * (NN + 1) + NN] = s_run;
}
__global__ void k_scatter(const int* __restrict__ src, const int* __restrict__ tgt) {
    int e = blockIdx.x * blockDim.x + threadIdx.x;
    if (e < BB * EE) {
        int b = e / EE;
        int t = tgt[e];
        int p = atomicAdd(&d_cur[b * NN + t], 1);
        d_es[(size_t)b * EE + p] = src[e];
    }
}

// ---------------------------------------------------------------------------
// Merged per-layer prep (also resets d_gmax for the layer):
//  blocks 0..15  : bf16 split of 0.25*W^T
//  blocks 16..19 : attention projection vectors
// ---------------------------------------------------------------------------
__global__ void __launch_bounds__(256) k_prep(const float* __restrict__ W,
                                              const float* __restrict__ as_,
                                              const float* __restrict__ ad_) {
    int blk = blockIdx.x;
    int t = threadIdx.x;
    if (blk == 16 && t < BB * NHEADS) d_gmax[t] = 0u;   // encoded "-inf"
    if (blk < 16) {
        int c = blk * 8 + (t >> 5);
        int kb = (t & 31) * 16;
        __nv_bfloat16 hi[16], lo[16];
        #pragma unroll
        for (int i = 0; i < 16; i++) {
            int k = kb + i;
            float val = 0.25f * W[(size_t)(k & 127) * HOUT + (k >> 7) * HH + c];
            __nv_bfloat16 h = __float2bfloat16_rn(val);
            hi[i] = h;
            lo[i] = __float2bfloat16_rn(val - __bfloat162float(h));
        }
        size_t base = (size_t)c * HOUT + kb;
        *(uint4*)&d_WThi[base]     = *(uint4*)&hi[0];
        *(uint4*)&d_WThi[base + 8] = *(uint4*)&hi[8];
        *(uint4*)&d_WTlo[base]     = *(uint4*)&lo[0];
        *(uint4*)&d_WTlo[base + 8] = *(uint4*)&lo[8];
    } else {
        int tt = (blk - 16) * 256 + t;       // 0..1023
        int c = tt >> 3;
        int q = tt & 7;
        int h = q & 3;
        bool is_d = (q >= 4);
        const float* a = is_d ? ad_ : as_;
        float sum = 0.f;
        const float* wr = W + (size_t)c * HOUT + h * HH;
        const float* ar = a + h * HH;
        #pragma unroll 8
        for (int k = 0; k < HH; k++) sum = fmaf(wr[k], ar[k], sum);
        if (is_d) d_Wd[c * NHEADS + h] = sum;
        else      d_Ws[c * NHEADS + h] = sum;
    }
}

// ---------------------------------------------------------------------------
// escore: warp per row. Also accumulates per-(batch,head) global max of esrc
// (block reduce + atomicMax on 16 addresses). A block's 8 rows share a batch
// (NN = 10000 = 1250*8, aligned).
// ---------------------------------------------------------------------------
__global__ void __launch_bounds__(256) k_escore(const float* __restrict__ Xin) {
    __shared__ float sWs[HH * NHEADS];
    __shared__ float sWd[HH * NHEADS];
    __shared__ float smx[8][4];
    int tid = threadIdx.x;
    sWs[tid] = d_Ws[tid]; sWs[tid + 256] = d_Ws[tid + 256];
    sWd[tid] = d_Wd[tid]; sWd[tid + 256] = d_Wd[tid + 256];
    __syncthreads();

    int row = blockIdx.x * 8 + (tid >> 5);
    int lane = tid & 31;
    float4 x = *(const float4*)&Xin[(size_t)row * HH + lane * 4];
    float xv[4] = {x.x, x.y, x.z, x.w};
    float p[8] = {0, 0, 0, 0, 0, 0, 0, 0};
    #pragma unroll
    for (int i = 0; i < 4; i++) {
        int c = lane * 4 + i;
        #pragma unroll
        for (int h = 0; h < 4; h++) {
            p[h]     = fmaf(xv[i], sWs[c * 4 + h], p[h]);
            p[4 + h] = fmaf(xv[i], sWd[c * 4 + h], p[4 + h]);
        }
    }
    #pragma unroll
    for (int s = 16; s > 0; s >>= 1) {
        #pragma unroll
        for (int q = 0; q < 8; q++)
            p[q] += __shfl_xor_sync(0xffffffffu, p[q], s);
    }
    if (lane == 0) {
        *(float4*)&d_esrc[row * 4] = make_float4(p[0], p[1], p[2], p[3]);
        *(float4*)&d_edst[row * 4] = make_float4(p[4], p[5], p[6], p[7]);
        smx[tid >> 5][0] = p[0];
        smx[tid >> 5][1] = p[1];
        smx[tid >> 5][2] = p[2];
        smx[tid >> 5][3] = p[3];
    }
    __syncthreads();
    if (tid < 4) {
        float m = smx[0][tid];
        #pragma unroll
        for (int i = 1; i < 8; i++) m = fmaxf(m, smx[i][tid]);
        int b = (blockIdx.x * 8) / NN;
        atomicMax(&d_gmax[b * NHEADS + tid], encf(m));
    }
}

// ---------------------------------------------------------------------------
// alpha: warp per node, ONE edge sweep. Uses global-max bound C (softmax is
// shift-invariant; C >= per-node max because lrelu is monotone). Stores
// unnormalized exps; normalization deferred to gather epilogue via d_ainv.
// ---------------------------------------------------------------------------
__global__ void __launch_bounds__(256) k_alpha() {
    int w = blockIdx.x * 8 + (threadIdx.x >> 5);
    int lane = threadIdx.x & 31;
    int b = w / NN;
    int n = w - b * NN;
    const int beg = d_off[b * (NN + 1) + n];
    const int cnte = d_off[b * (NN + 1) + n + 1] - beg;
    const size_t ebase = (size_t)b * EE + beg;

    float4 ed4 = *(const float4*)&d_edst[w * 4];
    float edv[4] = {ed4.x, ed4.y, ed4.z, ed4.w};
    float4 es4 = *(const float4*)&d_esrc[w * 4];
    float esf[4] = {es4.x, es4.y, es4.z, es4.w};

    float C[4];
    #pragma unroll
    for (int h = 0; h < 4; h++)
        C[h] = lrelu(decf(d_gmax[b * NHEADS + h]) + edv[h]);

    float e_self[4];
    #pragma unroll
    for (int h = 0; h < 4; h++) e_self[h] = lrelu(esf[h] + edv[h]);

    // single sweep: exp, store unnormalized, accumulate sum
    float sm[4] = {0, 0, 0, 0};
    for (int j = lane; j < cnte; j += 32) {
        int src = __ldg(&d_es[ebase + j]);
        float4 e4 = __ldg((const float4*)&d_esrc[((size_t)b * NN + src) * 4]);
        float ex[4];
        ex[0] = __expf(lrelu(e4.x + edv[0]) - C[0]);
        ex[1] = __expf(lrelu(e4.y + edv[1]) - C[1]);
        ex[2] = __expf(lrelu(e4.z + edv[2]) - C[2]);
        ex[3] = __expf(lrelu(e4.w + edv[3]) - C[3]);
        sm[0] += ex[0]; sm[1] += ex[1]; sm[2] += ex[2]; sm[3] += ex[3];
        *(float4*)&d_alpha[(ebase + j) * 4] = make_float4(ex[0], ex[1], ex[2], ex[3]);
    }
    #pragma unroll
    for (int s = 16; s > 0; s >>= 1)
        #pragma unroll
        for (int h = 0; h < 4; h++) sm[h] += __shfl_xor_sync(0xffffffffu, sm[h], s);

    if (lane == 0) {
        float ex_self[4], inv[4];
        #pragma unroll
        for (int h = 0; h < 4; h++) {
            ex_self[h] = __expf(e_self[h] - C[h]);
            inv[h] = 1.f / (sm[h] + ex_self[h]);
        }
        *(float4*)&d_aself[w * 4] = make_float4(ex_self[0], ex_self[1], ex_self[2], ex_self[3]);
        *(float4*)&d_ainv[w * 4]  = make_float4(inv[0], inv[1], inv[2], inv[3]);
    }
}

// ---------------------------------------------------------------------------
// gather: WARP per node (R13-proven loop). Accumulates unnormalized, applies
// 1/sum from d_ainv in the epilogue, writes bf16 hi/lo split.
// ---------------------------------------------------------------------------
__global__ void __launch_bounds__(256) k_gather(const float* __restrict__ Xin) {
    const int w = blockIdx.x * 8 + (threadIdx.x >> 5);   // node id
    const int lane = threadIdx.x & 31;
    const int b = w / NN;
    const int n = w - b * NN;
    const int beg = d_off[b * (NN + 1) + n];
    const int cnte = d_off[b * (NN + 1) + n + 1] - beg;
    const size_t ebase = (size_t)b * EE + beg;
    const float* Xb = Xin + (size_t)b * NN * HH;

    // self-loop init (unnormalized)
    float4 as_ = __ldg((const float4*)&d_aself[w * 4]);
    float4 xs = __ldg((const float4*)&Xb[(size_t)n * HH + lane * 4]);
    float4 a0, a1, a2, a3;
    a0.x = as_.x * xs.x; a0.y = as_.x * xs.y; a0.z = as_.x * xs.z; a0.w = as_.x * xs.w;
    a1.x = as_.y * xs.x; a1.y = as_.y * xs.y; a1.z = as_.y * xs.z; a1.w = as_.y * xs.w;
    a2.x = as_.z * xs.x; a2.y = as_.z * xs.y; a2.z = as_.z * xs.z; a2.w = as_.z * xs.w;
    a3.x = as_.w * xs.x; a3.y = as_.w * xs.y; a3.z = as_.w * xs.z; a3.w = as_.w * xs.w;

    #pragma unroll 4
    for (int j = 0; j < cnte; j++) {
        int src = __ldg(&d_es[ebase + j]);                                 // broadcast
        float4 al = __ldg((const float4*)&d_alpha[(ebase + j) * 4]);       // broadcast
        float4 x = __ldg((const float4*)&Xb[(size_t)src * HH + lane * 4]); // coalesced
        a0.x = fmaf(al.x, x.x, a0.x); a0.y = fmaf(al.x, x.y, a0.y);
        a0.z = fmaf(al.x, x.z, a0.z); a0.w = fmaf(al.x, x.w, a0.w);
        a1.x = fmaf(al.y, x.x, a1.x); a1.y = fmaf(al.y, x.y, a1.y);
        a1.z = fmaf(al.y, x.z, a1.z); a1.w = fmaf(al.y, x.w, a1.w);
        a2.x = fmaf(al.z, x.x, a2.x); a2.y = fmaf(al.z, x.y, a2.y);
        a2.z = fmaf(al.z, x.z, a2.z); a2.w = fmaf(al.z, x.w, a2.w);
        a3.x = fmaf(al.w, x.x, a3.x); a3.y = fmaf(al.w, x.y, a3.y);
        a3.z = fmaf(al.w, x.z, a3.z); a3.w = fmaf(al.w, x.w, a3.w);
    }

    // normalize
    float4 iv = __ldg((const float4*)&d_ainv[w * 4]);
    a0.x *= iv.x; a0.y *= iv.x; a0.z *= iv.x; a0.w *= iv.x;
    a1.x *= iv.y; a1.y *= iv.y; a1.z *= iv.y; a1.w *= iv.y;
    a2.x *= iv.z; a2.y *= iv.z; a2.z *= iv.z; a2.w *= iv.z;
    a3.x *= iv.w; a3.y *= iv.w; a3.z *= iv.w; a3.w *= iv.w;

    // bf16 hi/lo split write, per head
    size_t obase = (size_t)w * HOUT + lane * 4;
    float4 acc[4] = {a0, a1, a2, a3};
    #pragma unroll
    for (int h = 0; h < 4; h++) {
        float4 r = acc[h];
        float hx = __bfloat162float(__float2bfloat16_rn(r.x));
        float hy = __bfloat162float(__float2bfloat16_rn(r.y));
        float hz = __bfloat162float(__float2bfloat16_rn(r.z));
        float hw = __bfloat162float(__float2bfloat16_rn(r.w));
        uint32_t hi01 = packbf(r.x, r.y);
        uint32_t hi23 = packbf(r.z, r.w);
        uint32_t lo01 = packbf(r.x - hx, r.y - hy);
        uint32_t lo23 = packbf(r.z - hz, r.w - hw);
        *(uint2*)&d_Agghi[obase + h * HH] = make_uint2(hi01, hi23);
        *(uint2*)&d_Agglo[obase + h * HH] = make_uint2(lo01, lo23);
    }
}

// ---------------------------------------------------------------------------
// Tensor-core GEMM + fused epilogue. A is pre-split bf16 (no convert in loop).
// BM=128, BN=128, BK=32, 256 threads, 8 warps as 4(M)x2(N).
// ---------------------------------------------------------------------------
#define SPAD 40
__global__ void __launch_bounds__(256) k_gemm_tc(const float* __restrict__ bias,
                                                 const float* __restrict__ g,
                                                 const float* __restrict__ bparm,
                                                 float* __restrict__ outp,
                                                 int mode) {
    __shared__ __nv_bfloat16 sAhi[128 * SPAD];
    __shared__ __nv_bfloat16 sAlo[128 * SPAD];
    __shared__ __nv_bfloat16 sBhi[128 * SPAD];
    __shared__ __nv_bfloat16 sBlo[128 * SPAD];
    __shared__ float sred[2][2][128];

    const int tid  = threadIdx.x;
    const int lane = tid & 31;
    const int wid  = tid >> 5;
    const int wm   = wid & 3;
    const int wn   = wid >> 2;
    const int brow = blockIdx.x * 128;

    const int lr = tid >> 1;
    const int lk = (tid & 1) * 16;
    const int grow = brow + lr;
    const bool arow_ok = (grow < MTOT);

    float c[2][8][4];
    #pragma unroll
    for (int i = 0; i < 2; i++)
        #pragma unroll
        for (int j = 0; j < 8; j++)
            #pragma unroll
            for (int q = 0; q < 4; q++) c[i][j][q] = 0.f;

    const uint32_t uAhi = s2u(sAhi), uAlo = s2u(sAlo);
    const uint32_t uBhi = s2u(sBhi), uBlo = s2u(sBlo);

    uint4 ah0, ah1, al0, al1;
    uint4 bh0, bh1, bl0, bl1;
    const uint4 z4 = make_uint4(0, 0, 0, 0);

    {
        if (arow_ok) {
            const uint4* pah = (const uint4*)&d_Agghi[(size_t)grow * HOUT + lk];
            const uint4* pal = (const uint4*)&d_Agglo[(size_t)grow * HOUT + lk];
            ah0 = pah[0]; ah1 = pah[1];
            al0 = pal[0]; al1 = pal[1];
        } else {
            ah0 = ah1 = al0 = al1 = z4;
        }
        const uint4* pbh = (const uint4*)&d_WThi[(size_t)lr * HOUT + lk];
        const uint4* pbl = (const uint4*)&d_WTlo[(size_t)lr * HOUT + lk];
        bh0 = pbh[0]; bh1 = pbh[1];
        bl0 = pbl[0]; bl1 = pbl[1];
    }

    #pragma unroll 1
    for (int it = 0; it < HOUT / 32; it++) {
        {
            int so = lr * SPAD + lk;
            *(uint4*)&sAhi[so]     = ah0;
            *(uint4*)&sAhi[so + 8] = ah1;
            *(uint4*)&sAlo[so]     = al0;
            *(uint4*)&sAlo[so + 8] = al1;
            *(uint4*)&sBhi[so]     = bh0;
            *(uint4*)&sBhi[so + 8] = bh1;
            *(uint4*)&sBlo[so]     = bl0;
            *(uint4*)&sBlo[so + 8] = bl1;
        }
        __syncthreads();

        if (it + 1 < HOUT / 32) {
            int k0 = (it + 1) * 32;
            if (arow_ok) {
                const uint4* pah = (const uint4*)&d_Agghi[(size_t)grow * HOUT + k0 + lk];
                const uint4* pal = (const uint4*)&d_Agglo[(size_t)grow * HOUT + k0 + lk];
                ah0 = pah[0]; ah1 = pah[1];
                al0 = pal[0]; al1 = pal[1];
            }
            const uint4* pbh = (const uint4*)&d_WThi[(size_t)lr * HOUT + k0 + lk];
            const uint4* pbl = (const uint4*)&d_WTlo[(size_t)lr * HOUT + k0 + lk];
            bh0 = pbh[0]; bh1 = pbh[1];
            bl0 = pbl[0]; bl1 = pbl[1];
        }

        #pragma unroll
        for (int ks = 0; ks < 2; ks++) {
            const int kk = ks * 16;
            uint32_t ahi[2][4], alo[2][4];
            #pragma unroll
            for (int mt = 0; mt < 2; mt++) {
                int rb = wm * 32 + mt * 16;
                uint32_t off = 2u * ((rb + (lane & 15)) * SPAD + kk + (lane >> 4) * 8);
                ldsm4(ahi[mt], uAhi + off);
                ldsm4(alo[mt], uAlo + off);
            }
            #pragma unroll
            for (int np = 0; np < 4; np++) {
                int cb = wn * 64 + np * 16;
                uint32_t boff = 2u * ((cb + (lane >> 4) * 8 + (lane & 7)) * SPAD
                                      + kk + ((lane >> 3) & 1) * 8);
                uint32_t bh[4], bl[4];
                ldsm4(bh, uBhi + boff);
                ldsm4(bl, uBlo + boff);
                #pragma unroll
                for (int half = 0; half < 2; half++) {
                    int nt = np * 2 + half;
                    #pragma unroll
                    for (int mt = 0; mt < 2; mt++) {
                        mma16816(c[mt][nt], ahi[mt], &bh[half * 2]);
                        mma16816(c[mt][nt], ahi[mt], &bl[half * 2]);
                        mma16816(c[mt][nt], alo[mt], &bh[half * 2]);
                    }
                }
            }
        }
        __syncthreads();
    }

    // ---- fused epilogue ----
    const int colq = (lane & 3) * 2;

    #pragma unroll
    for (int nt = 0; nt < 8; nt++) {
        int col = wn * 64 + nt * 8 + colq;
        float b0 = __ldg(&bias[col]);
        float b1 = __ldg(&bias[col + 1]);
        #pragma unroll
        for (int mt = 0; mt < 2; mt++) {
            c[mt][nt][0] += b0; c[mt][nt][1] += b1;
            c[mt][nt][2] += b0; c[mt][nt][3] += b1;
        }
    }

    if (mode == 1) {
        #pragma unroll
        for (int mt = 0; mt < 2; mt++) {
            #pragma unroll
            for (int nt = 0; nt < 8; nt++) {
                int r0 = brow + wm * 32 + mt * 16 + (lane >> 2);
                int col = wn * 64 + nt * 8 + colq;
                if (r0 < MTOT)
                    *(float2*)&outp[(size_t)r0 * HH + col] = make_float2(c[mt][nt][0], c[mt][nt][1]);
                if (r0 + 8 < MTOT)
                    *(float2*)&outp[(size_t)(r0 + 8) * HH + col] = make_float2(c[mt][nt][2], c[mt][nt][3]);
            }
        }
        return;
    }

    // mean
    #pragma unroll
    for (int mt = 0; mt < 2; mt++) {
        float p0 = 0.f, p1 = 0.f;
        #pragma unroll
        for (int nt = 0; nt < 8; nt++) {
            p0 += c[mt][nt][0] + c[mt][nt][1];
            p1 += c[mt][nt][2] + c[mt][nt][3];
        }
        p0 += __shfl_xor_sync(0xffffffffu, p0, 1);
        p0 += __shfl_xor_sync(0xffffffffu, p0, 2);
        p1 += __shfl_xor_sync(0xffffffffu, p1, 1);
        p1 += __shfl_xor_sync(0xffffffffu, p1, 2);
        if ((lane & 3) == 0) {
            int r = wm * 32 + mt * 16 + (lane >> 2);
            sred[0][wn][r]     = p0;
            sred[0][wn][r + 8] = p1;
        }
    }
    __syncthreads();
    float mu[2][2];
    #pragma unroll
    for (int mt = 0; mt < 2; mt++) {
        int r = wm * 32 + mt * 16 + (lane >> 2);
        mu[mt][0] = (sred[0][0][r]     + sred[0][1][r])     * (1.f / 128.f);
        mu[mt][1] = (sred[0][0][r + 8] + sred[0][1][r + 8]) * (1.f / 128.f);
    }

    // variance
    #pragma unroll
    for (int mt = 0; mt < 2; mt++) {
        float p0 = 0.f, p1 = 0.f;
        #pragma unroll
        for (int nt = 0; nt < 8; nt++) {
            float d0 = c[mt][nt][0] - mu[mt][0];
            float d1 = c[mt][nt][1] - mu[mt][0];
            float d2 = c[mt][nt][2] - mu[mt][1];
            float d3 = c[mt][nt][3] - mu[mt][1];
            p0 += d0 * d0 + d1 * d1;
            p1 += d2 * d2 + d3 * d3;
        }
        p0 += __shfl_xor_sync(0xffffffffu, p0, 1);
        p0 += __shfl_xor_sync(0xffffffffu, p0, 2);
        p1 += __shfl_xor_sync(0xffffffffu, p1, 1);
        p1 += __shfl_xor_sync(0xffffffffu, p1, 2);
        if ((lane & 3) == 0) {
            int r = wm * 32 + mt * 16 + (lane >> 2);
            sred[1][wn][r]     = p0;
            sred[1][wn][r + 8] = p1;
        }
    }
    __syncthreads();
    float rst[2][2];
    #pragma unroll
    for (int mt = 0; mt < 2; mt++) {
        int r = wm * 32 + mt * 16 + (lane >> 2);
        rst[mt][0] = rsqrtf((sred[1][0][r]     + sred[1][1][r])     * (1.f / 128.f) + 1e-5f);
        rst[mt][1] = rsqrtf((sred[1][0][r + 8] + sred[1][1][r + 8]) * (1.f / 128.f) + 1e-5f);
    }

    // normalize + ReLU + store
    #pragma unroll
    for (int nt = 0; nt < 8; nt++) {
        int col = wn * 64 + nt * 8 + colq;
        float g0 = __ldg(&g[col]),      g1 = __ldg(&g[col + 1]);
        float q0 = __ldg(&bparm[col]),  q1 = __ldg(&bparm[col + 1]);
        #pragma unroll
        for (int mt = 0; mt < 2; mt++) {
            int r0 = brow + wm * 32 + mt * 16 + (lane >> 2);
            if (r0 < MTOT) {
                float o0 = fmaxf(fmaf((c[mt][nt][0] - mu[mt][0]) * rst[mt][0], g0, q0), 0.f);
                float o1 = fmaxf(fmaf((c[mt][nt][1] - mu[mt][0]) * rst[mt][0], g1, q1), 0.f);
                *(float2*)&d_X[(size_t)r0 * HH + col] = make_float2(o0, o1);
            }
            if (r0 + 8 < MTOT) {
                float o2 = fmaxf(fmaf((c[mt][nt][2] - mu[mt][1]) * rst[mt][1], g0, q0), 0.f);
                float o3 = fmaxf(fmaf((c[mt][nt][3] - mu[mt][1]) * rst[mt][1], g1, q1), 0.f);
                *(float2*)&d_X[(size_t)(r0 + 8) * HH + col] = make_float2(o2, o3);
            }
        }
    }
}

// ---------------------------------------------------------------------------
// Launch
// ---------------------------------------------------------------------------
extern "C" void kernel_launch(void* const* d_in, const int* in_sizes, int n_in,
                              void* d_out, int out_size) {
    const float* x0   = (const float*)d_in[0];
    const int*   src  = (const int*)d_in[1];
    const int*   tgt  = (const int*)d_in[2];
    const float* W1   = (const float*)d_in[3];
    const float* as1  = (const float*)d_in[4];
    const float* ad1  = (const float*)d_in[5];
    const float* b1   = (const float*)d_in[6];
    const float* W2   = (const float*)d_in[7];
    const float* as2  = (const float*)d_in[8];
    const float* ad2  = (const float*)d_in[9];
    const float* b2   = (const float*)d_in[10];
    const float* W3   = (const float*)d_in[11];
    const float* as3  = (const float*)d_in[12];
    const float* ad3  = (const float*)d_in[13];
    const float* b3   = (const float*)d_in[14];
    const float* g1   = (const float*)d_in[15];
    const float* bb1  = (const float*)d_in[16];
    const float* g2   = (const float*)d_in[17];
    const float* bb2  = (const float*)d_in[18];
    float* out = (float*)d_out;

    float* d_X_ptr;
    cudaGetSymbolAddress((void**)&d_X_ptr, d_X);

    // ---- CSR build ----
    k_zero_cnt<<<(BB * (NN + 1) + 255) / 256, 256>>>();
    k_hist<<<(BB * EE + 255) / 256, 256>>>(tgt);
    k_scan<<<BB, 1024>>>();
    k_scatter<<<(BB * EE + 255) / 256, 256>>>(src, tgt);

    const int gw = MTOT / 8;             // warp-per-node grids (5000)
    const int gm = (MTOT + 127) / 128;

    // ---- Layer 1 ----
    k_prep<<<20, 256>>>(W1, as1, ad1);
    k_escore<<<gw, 256>>>(x0);
    k_alpha<<<gw, 256>>>();
    k_gather<<<gw, 256>>>(x0);
    k_gemm_tc<<<gm, 256>>>(b1, g1, bb1, nullptr, 0);

    // ---- Layer 2 ----
    k_prep<<<20, 256>>>(W2, as2, ad2);
    k_escore<<<gw, 256>>>(d_X_ptr);
    k_alpha<<<gw, 256>>>();
    k_gather<<<gw, 256>>>(d_X_ptr);
    k_gemm_tc<<<gm, 256>>>(b2, g2, bb2, nullptr, 0);

    // ---- Layer 3 ----
    k_prep<<<20, 256>>>(W3, as3, ad3);
    k_escore<<<gw, 256>>>(d_X_ptr);
    k_alpha<<<gw, 256>>>();
    k_gather<<<gw, 256>>>(d_X_ptr);
    k_gemm_tc<<<gm, 256>>>(b3, nullptr, nullptr, out, 1);
}

// round 16
// speedup vs baseline: 1.1138x; 1.0306x over previous
#include <cuda_runtime.h>
#include <cuda_bf16.h>
#include <cstdint>

// Problem constants
#define BB      4
#define NN      10000
#define EE      160000
#define HH      128
#define NHEADS  4
#define HOUT    512      // NHEADS * HH
#define MTOT    (BB*NN)  // 40000 rows

// ---------------------------------------------------------------------------
// Static device scratch
// ---------------------------------------------------------------------------
__device__ __nv_bfloat16 d_Agghi[(size_t)BB * NN * HOUT]; // aggregated X, bf16 hi
__device__ __nv_bfloat16 d_Agglo[(size_t)BB * NN * HOUT]; // aggregated X, bf16 lo
__device__ float d_X[(size_t)BB * NN * HH];         // layer activations  [B*N, 128]
__device__ float d_esrc[BB * NN * NHEADS];
__device__ float d_edst[BB * NN * NHEADS];
__device__ float d_alpha[(size_t)BB * EE * NHEADS]; // UNNORMALIZED exp weights
__device__ float d_aself[BB * NN * NHEADS];         // unnormalized self exp
__device__ float d_ainv[BB * NN * NHEADS];          // per-node 1/sum
__device__ unsigned d_gmax[BB * NHEADS];            // encoded global max of esrc
__device__ int   d_cnt[BB * (NN + 1)];
__device__ int   d_off[BB * (NN + 1)];
__device__ int   d_cur[BB * NN];
__device__ int   d_es [BB * EE];
__device__ float d_Ws[HH * NHEADS];
__device__ float d_Wd[HH * NHEADS];
__device__ __nv_bfloat16 d_WThi[HH * HOUT];         // W^T split, [c=128][k=512], 0.25 folded
__device__ __nv_bfloat16 d_WTlo[HH * HOUT];

__device__ __forceinline__ float lrelu(float x) { return x > 0.f ? x : 0.2f * x; }

// monotone float<->uint encoding for atomicMax on floats (any sign)
__device__ __forceinline__ unsigned encf(float f) {
    unsigned u = __float_as_uint(f);
    return (u & 0x80000000u) ? ~u : (u | 0x80000000u);
}
__device__ __forceinline__ float decf(unsigned e) {
    return (e & 0x80000000u) ? __uint_as_float(e & 0x7fffffffu) : __uint_as_float(~e);
}

__device__ __forceinline__ uint32_t s2u(const void* p) {
    return (uint32_t)__cvta_generic_to_shared(p);
}
__device__ __forceinline__ uint32_t packbf(float x, float y) {
    __nv_bfloat162 t = __floats2bfloat162_rn(x, y);
    return *(uint32_t*)&t;
}
__device__ __forceinline__ void ldsm4(uint32_t* r, uint32_t addr) {
    asm volatile("ldmatrix.sync.aligned.m8n8.x4.shared.b16 {%0,%1,%2,%3}, [%4];\n"
                 : "=r"(r[0]), "=r"(r[1]), "=r"(r[2]), "=r"(r[3]) : "r"(addr));
}
__device__ __forceinline__ void mma16816(float* c, const uint32_t* a, const uint32_t* b) {
    asm volatile("mma.sync.aligned.m16n8k16.row.col.f32.bf16.bf16.f32 "
                 "{%0,%1,%2,%3}, {%4,%5,%6,%7}, {%8,%9}, {%0,%1,%2,%3};\n"
                 : "+f"(c[0]), "+f"(c[1]), "+f"(c[2]), "+f"(c[3])
                 : "r"(a[0]), "r"(a[1]), "r"(a[2]), "r"(a[3]), "r"(b[0]), "r"(b[1]));
}

// ---------------------------------------------------------------------------
// CSR build (zero via memset node; scan rewritten as 3-sync shuffle scan)
// ---------------------------------------------------------------------------
__global__ void k_hist(const int* __restrict__ tgt) {
    int e = blockIdx.x * blockDim.x + threadIdx.x;
    if (e < BB * EE) {
        int b = e / EE;
        atomicAdd(&d_cnt[b * (NN + 1) + tgt[e]], 1);
    }
}

// One block per batch, 1024 threads, 10 elements/thread, shuffle-based scan.
__global__ void __launch_bounds__(1024) k_scan() {
    const int b = blockIdx.x;
    const int t = threadIdx.x;
    const int lane = t & 31;
    const int wid = t >> 5;
    const int base = t * 10;

    int c[10];
    int s = 0;
    if (base < NN) {
        #pragma unroll
        for (int i = 0; i < 10; i++) {
            int idx = base + i;
            int v = (idx < NN) ? d_cnt[b * (NN + 1) + idx] : 0;
            c[i] = s;                 // exclusive prefix within thread
            s += v;
        }
    }
    // warp inclusive scan of thread sums
    int ss = s;
    #pragma unroll
    for (int o = 1; o < 32; o <<= 1) {
        int v = __shfl_up_sync(0xffffffffu, ss, o);
        if (lane >= o) ss += v;
    }
    __shared__ int wsum[32];
    if (lane == 31) wsum[wid] = ss;
    __syncthreads();
    if (wid == 0) {
        int v = wsum[lane];
        #pragma unroll
        for (int o = 1; o < 32; o <<= 1) {
            int u = __shfl_up_sync(0xffffffffu, v, o);
            if (lane >= o) v += u;
        }
        wsum[lane] = v;               // inclusive warp totals
    }
    __syncthreads();
    int warpoff = (wid > 0) ? wsum[wid - 1] : 0;
    int texcl = warpoff + ss - s;     // exclusive prefix of this thread
    if (base < NN) {
        #pragma unroll
        for (int i = 0; i < 10; i++) {
            int idx = base + i;
            if (idx < NN) {
                int e = texcl + c[i];
                d_off[b * (NN + 1) + idx] = e;
                d_cur[b * NN + idx]       = e;
            }
        }
    }
    if (t == 1023) d_off[b * (NN + 1) + NN] = wsum[31];
}

__global__ void k_scatter(const int* __restrict__ src, const int* __restrict__ tgt) {
    int e = blockIdx.x * blockDim.x + threadIdx.x;
    if (e < BB * EE) {
        int b = e / EE;
        int t = tgt[e];
        int p = atomicAdd(&d_cur[b * NN + t], 1);
        d_es[(size_t)b * EE + p] = src[e];
    }
}

// ---------------------------------------------------------------------------
// Merged per-layer prep (also resets d_gmax for the layer):
//  blocks 0..15  : bf16 split of 0.25*W^T
//  blocks 16..19 : attention projection vectors
// ---------------------------------------------------------------------------
__global__ void __launch_bounds__(256) k_prep(const float* __restrict__ W,
                                              const float* __restrict__ as_,
                                              const float* __restrict__ ad_) {
    int blk = blockIdx.x;
    int t = threadIdx.x;
    if (blk == 16 && t < BB * NHEADS) d_gmax[t] = 0u;   // encoded "-inf"
    if (blk < 16) {
        int c = blk * 8 + (t >> 5);
        int kb = (t & 31) * 16;
        __nv_bfloat16 hi[16], lo[16];
        #pragma unroll
        for (int i = 0; i < 16; i++) {
            int k = kb + i;
            float val = 0.25f * W[(size_t)(k & 127) * HOUT + (k >> 7) * HH + c];
            __nv_bfloat16 h = __float2bfloat16_rn(val);
            hi[i] = h;
            lo[i] = __float2bfloat16_rn(val - __bfloat162float(h));
        }
        size_t base = (size_t)c * HOUT + kb;
        *(uint4*)&d_WThi[base]     = *(uint4*)&hi[0];
        *(uint4*)&d_WThi[base + 8] = *(uint4*)&hi[8];
        *(uint4*)&d_WTlo[base]     = *(uint4*)&lo[0];
        *(uint4*)&d_WTlo[base + 8] = *(uint4*)&lo[8];
    } else {
        int tt = (blk - 16) * 256 + t;       // 0..1023
        int c = tt >> 3;
        int q = tt & 7;
        int h = q & 3;
        bool is_d = (q >= 4);
        const float* a = is_d ? ad_ : as_;
        float sum = 0.f;
        const float* wr = W + (size_t)c * HOUT + h * HH;
        const float* ar = a + h * HH;
        #pragma unroll 8
        for (int k = 0; k < HH; k++) sum = fmaf(wr[k], ar[k], sum);
        if (is_d) d_Wd[c * NHEADS + h] = sum;
        else      d_Ws[c * NHEADS + h] = sum;
    }
}

// ---------------------------------------------------------------------------
// escore: warp per row; accumulates per-(batch,head) global max of esrc.
// ---------------------------------------------------------------------------
__global__ void __launch_bounds__(256) k_escore(const float* __restrict__ Xin) {
    __shared__ float sWs[HH * NHEADS];
    __shared__ float sWd[HH * NHEADS];
    __shared__ float smx[8][4];
    int tid = threadIdx.x;
    sWs[tid] = d_Ws[tid]; sWs[tid + 256] = d_Ws[tid + 256];
    sWd[tid] = d_Wd[tid]; sWd[tid + 256] = d_Wd[tid + 256];
    __syncthreads();

    int row = blockIdx.x * 8 + (tid >> 5);
    int lane = tid & 31;
    float4 x = *(const float4*)&Xin[(size_t)row * HH + lane * 4];
    float xv[4] = {x.x, x.y, x.z, x.w};
    float p[8] = {0, 0, 0, 0, 0, 0, 0, 0};
    #pragma unroll
    for (int i = 0; i < 4; i++) {
        int c = lane * 4 + i;
        #pragma unroll
        for (int h = 0; h < 4; h++) {
            p[h]     = fmaf(xv[i], sWs[c * 4 + h], p[h]);
            p[4 + h] = fmaf(xv[i], sWd[c * 4 + h], p[4 + h]);
        }
    }
    #pragma unroll
    for (int s = 16; s > 0; s >>= 1) {
        #pragma unroll
        for (int q = 0; q < 8; q++)
            p[q] += __shfl_xor_sync(0xffffffffu, p[q], s);
    }
    if (lane == 0) {
        *(float4*)&d_esrc[row * 4] = make_float4(p[0], p[1], p[2], p[3]);
        *(float4*)&d_edst[row * 4] = make_float4(p[4], p[5], p[6], p[7]);
        smx[tid >> 5][0] = p[0];
        smx[tid >> 5][1] = p[1];
        smx[tid >> 5][2] = p[2];
        smx[tid >> 5][3] = p[3];
    }
    __syncthreads();
    if (tid < 4) {
        float m = smx[0][tid];
        #pragma unroll
        for (int i = 1; i < 8; i++) m = fmaxf(m, smx[i][tid]);
        int b = (blockIdx.x * 8) / NN;
        atomicMax(&d_gmax[b * NHEADS + tid], encf(m));
    }
}

// ---------------------------------------------------------------------------
// alpha: warp per node, ONE edge sweep (global-max bound C).
// ---------------------------------------------------------------------------
__global__ void __launch_bounds__(256) k_alpha() {
    int w = blockIdx.x * 8 + (threadIdx.x >> 5);
    int lane = threadIdx.x & 31;
    int b = w / NN;
    int n = w - b * NN;
    const int beg = d_off[b * (NN + 1) + n];
    const int cnte = d_off[b * (NN + 1) + n + 1] - beg;
    const size_t ebase = (size_t)b * EE + beg;

    float4 ed4 = *(const float4*)&d_edst[w * 4];
    float edv[4] = {ed4.x, ed4.y, ed4.z, ed4.w};
    float4 es4 = *(const float4*)&d_esrc[w * 4];
    float esf[4] = {es4.x, es4.y, es4.z, es4.w};

    float C[4];
    #pragma unroll
    for (int h = 0; h < 4; h++)
        C[h] = lrelu(decf(d_gmax[b * NHEADS + h]) + edv[h]);

    float e_self[4];
    #pragma unroll
    for (int h = 0; h < 4; h++) e_self[h] = lrelu(esf[h] + edv[h]);

    float sm[4] = {0, 0, 0, 0};
    for (int j = lane; j < cnte; j += 32) {
        int src = __ldg(&d_es[ebase + j]);
        float4 e4 = __ldg((const float4*)&d_esrc[((size_t)b * NN + src) * 4]);
        float ex[4];
        ex[0] = __expf(lrelu(e4.x + edv[0]) - C[0]);
        ex[1] = __expf(lrelu(e4.y + edv[1]) - C[1]);
        ex[2] = __expf(lrelu(e4.z + edv[2]) - C[2]);
        ex[3] = __expf(lrelu(e4.w + edv[3]) - C[3]);
        sm[0] += ex[0]; sm[1] += ex[1]; sm[2] += ex[2]; sm[3] += ex[3];
        *(float4*)&d_alpha[(ebase + j) * 4] = make_float4(ex[0], ex[1], ex[2], ex[3]);
    }
    #pragma unroll
    for (int s = 16; s > 0; s >>= 1)
        #pragma unroll
        for (int h = 0; h < 4; h++) sm[h] += __shfl_xor_sync(0xffffffffu, sm[h], s);

    if (lane == 0) {
        float ex_self[4], inv[4];
        #pragma unroll
        for (int h = 0; h < 4; h++) {
            ex_self[h] = __expf(e_self[h] - C[h]);
            inv[h] = 1.f / (sm[h] + ex_self[h]);
        }
        *(float4*)&d_aself[w * 4] = make_float4(ex_self[0], ex_self[1], ex_self[2], ex_self[3]);
        *(float4*)&d_ainv[w * 4]  = make_float4(inv[0], inv[1], inv[2], inv[3]);
    }
}

// ---------------------------------------------------------------------------
// gather: WARP per node (R13-proven loop), normalize in epilogue.
// ---------------------------------------------------------------------------
__global__ void __launch_bounds__(256) k_gather(const float* __restrict__ Xin) {
    const int w = blockIdx.x * 8 + (threadIdx.x >> 5);
    const int lane = threadIdx.x & 31;
    const int b = w / NN;
    const int n = w - b * NN;
    const int beg = d_off[b * (NN + 1) + n];
    const int cnte = d_off[b * (NN + 1) + n + 1] - beg;
    const size_t ebase = (size_t)b * EE + beg;
    const float* Xb = Xin + (size_t)b * NN * HH;

    float4 as_ = __ldg((const float4*)&d_aself[w * 4]);
    float4 xs = __ldg((const float4*)&Xb[(size_t)n * HH + lane * 4]);
    float4 a0, a1, a2, a3;
    a0.x = as_.x * xs.x; a0.y = as_.x * xs.y; a0.z = as_.x * xs.z; a0.w = as_.x * xs.w;
    a1.x = as_.y * xs.x; a1.y = as_.y * xs.y; a1.z = as_.y * xs.z; a1.w = as_.y * xs.w;
    a2.x = as_.z * xs.x; a2.y = as_.z * xs.y; a2.z = as_.z * xs.z; a2.w = as_.z * xs.w;
    a3.x = as_.w * xs.x; a3.y = as_.w * xs.y; a3.z = as_.w * xs.z; a3.w = as_.w * xs.w;

    #pragma unroll 4
    for (int j = 0; j < cnte; j++) {
        int src = __ldg(&d_es[ebase + j]);
        float4 al = __ldg((const float4*)&d_alpha[(ebase + j) * 4]);
        float4 x = __ldg((const float4*)&Xb[(size_t)src * HH + lane * 4]);
        a0.x = fmaf(al.x, x.x, a0.x); a0.y = fmaf(al.x, x.y, a0.y);
        a0.z = fmaf(al.x, x.z, a0.z); a0.w = fmaf(al.x, x.w, a0.w);
        a1.x = fmaf(al.y, x.x, a1.x); a1.y = fmaf(al.y, x.y, a1.y);
        a1.z = fmaf(al.y, x.z, a1.z); a1.w = fmaf(al.y, x.w, a1.w);
        a2.x = fmaf(al.z, x.x, a2.x); a2.y = fmaf(al.z, x.y, a2.y);
        a2.z = fmaf(al.z, x.z, a2.z); a2.w = fmaf(al.z, x.w, a2.w);
        a3.x = fmaf(al.w, x.x, a3.x); a3.y = fmaf(al.w, x.y, a3.y);
        a3.z = fmaf(al.w, x.z, a3.z); a3.w = fmaf(al.w, x.w, a3.w);
    }

    float4 iv = __ldg((const float4*)&d_ainv[w * 4]);
    a0.x *= iv.x; a0.y *= iv.x; a0.z *= iv.x; a0.w *= iv.x;
    a1.x *= iv.y; a1.y *= iv.y; a1.z *= iv.y; a1.w *= iv.y;
    a2.x *= iv.z; a2.y *= iv.z; a2.z *= iv.z; a2.w *= iv.z;
    a3.x *= iv.w; a3.y *= iv.w; a3.z *= iv.w; a3.w *= iv.w;

    size_t obase = (size_t)w * HOUT + lane * 4;
    float4 acc[4] = {a0, a1, a2, a3};
    #pragma unroll
    for (int h = 0; h < 4; h++) {
        float4 r = acc[h];
        float hx = __bfloat162float(__float2bfloat16_rn(r.x));
        float hy = __bfloat162float(__float2bfloat16_rn(r.y));
        float hz = __bfloat162float(__float2bfloat16_rn(r.z));
        float hw = __bfloat162float(__float2bfloat16_rn(r.w));
        uint32_t hi01 = packbf(r.x, r.y);
        uint32_t hi23 = packbf(r.z, r.w);
        uint32_t lo01 = packbf(r.x - hx, r.y - hy);
        uint32_t lo23 = packbf(r.z - hz, r.w - hw);
        *(uint2*)&d_Agghi[obase + h * HH] = make_uint2(hi01, hi23);
        *(uint2*)&d_Agglo[obase + h * HH] = make_uint2(lo01, lo23);
    }
}

// ---------------------------------------------------------------------------
// Tensor-core GEMM + fused epilogue. A is pre-split bf16.
// ---------------------------------------------------------------------------
#define SPAD 40
__global__ void __launch_bounds__(256) k_gemm_tc(const float* __restrict__ bias,
                                                 const float* __restrict__ g,
                                                 const float* __restrict__ bparm,
                                                 float* __restrict__ outp,
                                                 int mode) {
    __shared__ __nv_bfloat16 sAhi[128 * SPAD];
    __shared__ __nv_bfloat16 sAlo[128 * SPAD];
    __shared__ __nv_bfloat16 sBhi[128 * SPAD];
    __shared__ __nv_bfloat16 sBlo[128 * SPAD];
    __shared__ float sred[2][2][128];

    const int tid  = threadIdx.x;
    const int lane = tid & 31;
    const int wid  = tid >> 5;
    const int wm   = wid & 3;
    const int wn   = wid >> 2;
    const int brow = blockIdx.x * 128;

    const int lr = tid >> 1;
    const int lk = (tid & 1) * 16;
    const int grow = brow + lr;
    const bool arow_ok = (grow < MTOT);

    float c[2][8][4];
    #pragma unroll
    for (int i = 0; i < 2; i++)
        #pragma unroll
        for (int j = 0; j < 8; j++)
            #pragma unroll
            for (int q = 0; q < 4; q++) c[i][j][q] = 0.f;

    const uint32_t uAhi = s2u(sAhi), uAlo = s2u(sAlo);
    const uint32_t uBhi = s2u(sBhi), uBlo = s2u(sBlo);

    uint4 ah0, ah1, al0, al1;
    uint4 bh0, bh1, bl0, bl1;
    const uint4 z4 = make_uint4(0, 0, 0, 0);

    {
        if (arow_ok) {
            const uint4* pah = (const uint4*)&d_Agghi[(size_t)grow * HOUT + lk];
            const uint4* pal = (const uint4*)&d_Agglo[(size_t)grow * HOUT + lk];
            ah0 = pah[0]; ah1 = pah[1];
            al0 = pal[0]; al1 = pal[1];
        } else {
            ah0 = ah1 = al0 = al1 = z4;
        }
        const uint4* pbh = (const uint4*)&d_WThi[(size_t)lr * HOUT + lk];
        const uint4* pbl = (const uint4*)&d_WTlo[(size_t)lr * HOUT + lk];
        bh0 = pbh[0]; bh1 = pbh[1];
        bl0 = pbl[0]; bl1 = pbl[1];
    }

    #pragma unroll 1
    for (int it = 0; it < HOUT / 32; it++) {
        {
            int so = lr * SPAD + lk;
            *(uint4*)&sAhi[so]     = ah0;
            *(uint4*)&sAhi[so + 8] = ah1;
            *(uint4*)&sAlo[so]     = al0;
            *(uint4*)&sAlo[so + 8] = al1;
            *(uint4*)&sBhi[so]     = bh0;
            *(uint4*)&sBhi[so + 8] = bh1;
            *(uint4*)&sBlo[so]     = bl0;
            *(uint4*)&sBlo[so + 8] = bl1;
        }
        __syncthreads();

        if (it + 1 < HOUT / 32) {
            int k0 = (it + 1) * 32;
            if (arow_ok) {
                const uint4* pah = (const uint4*)&d_Agghi[(size_t)grow * HOUT + k0 + lk];
                const uint4* pal = (const uint4*)&d_Agglo[(size_t)grow * HOUT + k0 + lk];
                ah0 = pah[0]; ah1 = pah[1];
                al0 = pal[0]; al1 = pal[1];
            }
            const uint4* pbh = (const uint4*)&d_WThi[(size_t)lr * HOUT + k0 + lk];
            const uint4* pbl = (const uint4*)&d_WTlo[(size_t)lr * HOUT + k0 + lk];
            bh0 = pbh[0]; bh1 = pbh[1];
            bl0 = pbl[0]; bl1 = pbl[1];
        }

        #pragma unroll
        for (int ks = 0; ks < 2; ks++) {
            const int kk = ks * 16;
            uint32_t ahi[2][4], alo[2][4];
            #pragma unroll
            for (int mt = 0; mt < 2; mt++) {
                int rb = wm * 32 + mt * 16;
                uint32_t off = 2u * ((rb + (lane & 15)) * SPAD + kk + (lane >> 4) * 8);
                ldsm4(ahi[mt], uAhi + off);
                ldsm4(alo[mt], uAlo + off);
            }
            #pragma unroll
            for (int np = 0; np < 4; np++) {
                int cb = wn * 64 + np * 16;
                uint32_t boff = 2u * ((cb + (lane >> 4) * 8 + (lane & 7)) * SPAD
                                      + kk + ((lane >> 3) & 1) * 8);
                uint32_t bh[4], bl[4];
                ldsm4(bh, uBhi + boff);
                ldsm4(bl, uBlo + boff);
                #pragma unroll
                for (int half = 0; half < 2; half++) {
                    int nt = np * 2 + half;
                    #pragma unroll
                    for (int mt = 0; mt < 2; mt++) {
                        mma16816(c[mt][nt], ahi[mt], &bh[half * 2]);
                        mma16816(c[mt][nt], ahi[mt], &bl[half * 2]);
                        mma16816(c[mt][nt], alo[mt], &bh[half * 2]);
                    }
                }
            }
        }
        __syncthreads();
    }

    // ---- fused epilogue ----
    const int colq = (lane & 3) * 2;

    #pragma unroll
    for (int nt = 0; nt < 8; nt++) {
        int col = wn * 64 + nt * 8 + colq;
        float b0 = __ldg(&bias[col]);
        float b1 = __ldg(&bias[col + 1]);
        #pragma unroll
        for (int mt = 0; mt < 2; mt++) {
            c[mt][nt][0] += b0; c[mt][nt][1] += b1;
            c[mt][nt][2] += b0; c[mt][nt][3] += b1;
        }
    }

    if (mode == 1) {
        #pragma unroll
        for (int mt = 0; mt < 2; mt++) {
            #pragma unroll
            for (int nt = 0; nt < 8; nt++) {
                int r0 = brow + wm * 32 + mt * 16 + (lane >> 2);
                int col = wn * 64 + nt * 8 + colq;
                if (r0 < MTOT)
                    *(float2*)&outp[(size_t)r0 * HH + col] = make_float2(c[mt][nt][0], c[mt][nt][1]);
                if (r0 + 8 < MTOT)
                    *(float2*)&outp[(size_t)(r0 + 8) * HH + col] = make_float2(c[mt][nt][2], c[mt][nt][3]);
            }
        }
        return;
    }

    // mean
    #pragma unroll
    for (int mt = 0; mt < 2; mt++) {
        float p0 = 0.f, p1 = 0.f;
        #pragma unroll
        for (int nt = 0; nt < 8; nt++) {
            p0 += c[mt][nt][0] + c[mt][nt][1];
            p1 += c[mt][nt][2] + c[mt][nt][3];
        }
        p0 += __shfl_xor_sync(0xffffffffu, p0, 1);
        p0 += __shfl_xor_sync(0xffffffffu, p0, 2);
        p1 += __shfl_xor_sync(0xffffffffu, p1, 1);
        p1 += __shfl_xor_sync(0xffffffffu, p1, 2);
        if ((lane & 3) == 0) {
            int r = wm * 32 + mt * 16 + (lane >> 2);
            sred[0][wn][r]     = p0;
            sred[0][wn][r + 8] = p1;
        }
    }
    __syncthreads();
    float mu[2][2];
    #pragma unroll
    for (int mt = 0; mt < 2; mt++) {
        int r = wm * 32 + mt * 16 + (lane >> 2);
        mu[mt][0] = (sred[0][0][r]     + sred[0][1][r])     * (1.f / 128.f);
        mu[mt][1] = (sred[0][0][r + 8] + sred[0][1][r + 8]) * (1.f / 128.f);
    }

    // variance
    #pragma unroll
    for (int mt = 0; mt < 2; mt++) {
        float p0 = 0.f, p1 = 0.f;
        #pragma unroll
        for (int nt = 0; nt < 8; nt++) {
            float d0 = c[mt][nt][0] - mu[mt][0];
            float d1 = c[mt][nt][1] - mu[mt][0];
            float d2 = c[mt][nt][2] - mu[mt][1];
            float d3 = c[mt][nt][3] - mu[mt][1];
            p0 += d0 * d0 + d1 * d1;
            p1 += d2 * d2 + d3 * d3;
        }
        p0 += __shfl_xor_sync(0xffffffffu, p0, 1);
        p0 += __shfl_xor_sync(0xffffffffu, p0, 2);
        p1 += __shfl_xor_sync(0xffffffffu, p1, 1);
        p1 += __shfl_xor_sync(0xffffffffu, p1, 2);
        if ((lane & 3) == 0) {
            int r = wm * 32 + mt * 16 + (lane >> 2);
            sred[1][wn][r]     = p0;
            sred[1][wn][r + 8] = p1;
        }
    }
    __syncthreads();
    float rst[2][2];
    #pragma unroll
    for (int mt = 0; mt < 2; mt++) {
        int r = wm * 32 + mt * 16 + (lane >> 2);
        rst[mt][0] = rsqrtf((sred[1][0][r]     + sred[1][1][r])     * (1.f / 128.f) + 1e-5f);
        rst[mt][1] = rsqrtf((sred[1][0][r + 8] + sred[1][1][r + 8]) * (1.f / 128.f) + 1e-5f);
    }

    // normalize + ReLU + store
    #pragma unroll
    for (int nt = 0; nt < 8; nt++) {
        int col = wn * 64 + nt * 8 + colq;
        float g0 = __ldg(&g[col]),      g1 = __ldg(&g[col + 1]);
        float q0 = __ldg(&bparm[col]),  q1 = __ldg(&bparm[col + 1]);
        #pragma unroll
        for (int mt = 0; mt < 2; mt++) {
            int r0 = brow + wm * 32 + mt * 16 + (lane >> 2);
            if (r0 < MTOT) {
                float o0 = fmaxf(fmaf((c[mt][nt][0] - mu[mt][0]) * rst[mt][0], g0, q0), 0.f);
                float o1 = fmaxf(fmaf((c[mt][nt][1] - mu[mt][0]) * rst[mt][0], g1, q1), 0.f);
                *(float2*)&d_X[(size_t)r0 * HH + col] = make_float2(o0, o1);
            }
            if (r0 + 8 < MTOT) {
                float o2 = fmaxf(fmaf((c[mt][nt][2] - mu[mt][1]) * rst[mt][1], g0, q0), 0.f);
                float o3 = fmaxf(fmaf((c[mt][nt][3] - mu[mt][1]) * rst[mt][1], g1, q1), 0.f);
                *(float2*)&d_X[(size_t)(r0 + 8) * HH + col] = make_float2(o2, o3);
            }
        }
    }
}

// ---------------------------------------------------------------------------
// Launch (CSR build forked onto a side stream, overlapping layer-1 prep+escore)
// ---------------------------------------------------------------------------
extern "C" void kernel_launch(void* const* d_in, const int* in_sizes, int n_in,
                              void* d_out, int out_size) {
    const float* x0   = (const float*)d_in[0];
    const int*   src  = (const int*)d_in[1];
    const int*   tgt  = (const int*)d_in[2];
    const float* W1   = (const float*)d_in[3];
    const float* as1  = (const float*)d_in[4];
    const float* ad1  = (const float*)d_in[5];
    const float* b1   = (const float*)d_in[6];
    const float* W2   = (const float*)d_in[7];
    const float* as2  = (const float*)d_in[8];
    const float* ad2  = (const float*)d_in[9];
    const float* b2   = (const float*)d_in[10];
    const float* W3   = (const float*)d_in[11];
    const float* as3  = (const float*)d_in[12];
    const float* ad3  = (const float*)d_in[13];
    const float* b3   = (const float*)d_in[14];
    const float* g1   = (const float*)d_in[15];
    const float* bb1  = (const float*)d_in[16];
    const float* g2   = (const float*)d_in[17];
    const float* bb2  = (const float*)d_in[18];
    float* out = (float*)d_out;

    float* d_X_ptr;
    cudaGetSymbolAddress((void**)&d_X_ptr, d_X);
    int* d_cnt_ptr;
    cudaGetSymbolAddress((void**)&d_cnt_ptr, d_cnt);

    // lazily-created side stream + events (created on first, uncaptured, call)
    static cudaStream_t s2 = nullptr;
    static cudaEvent_t ev0 = nullptr, ev1 = nullptr;
    if (!s2) {
        cudaStreamCreateWithFlags(&s2, cudaStreamNonBlocking);
        cudaEventCreateWithFlags(&ev0, cudaEventDisableTiming);
        cudaEventCreateWithFlags(&ev1, cudaEventDisableTiming);
    }

    const int gw = MTOT / 8;             // warp-per-node grids (5000)
    const int gm = (MTOT + 127) / 128;

    // ---- fork: CSR build on side stream ----
    cudaEventRecord(ev0, 0);
    cudaStreamWaitEvent(s2, ev0, 0);
    cudaMemsetAsync(d_cnt_ptr, 0, sizeof(int) * BB * (NN + 1), s2);
    k_hist<<<(BB * EE + 255) / 256, 256, 0, s2>>>(tgt);
    k_scan<<<BB, 1024, 0, s2>>>();
    k_scatter<<<(BB * EE + 255) / 256, 256, 0, s2>>>(src, tgt);
    cudaEventRecord(ev1, s2);

    // ---- main stream: layer-1 prep + escore (independent of CSR) ----
    k_prep<<<20, 256>>>(W1, as1, ad1);
    k_escore<<<gw, 256>>>(x0);

    // ---- join before alpha ----
    cudaStreamWaitEvent(0, ev1, 0);

    // ---- Layer 1 ----
    k_alpha<<<gw, 256>>>();
    k_gather<<<gw, 256>>>(x0);
    k_gemm_tc<<<gm, 256>>>(b1, g1, bb1, nullptr, 0);

    // ---- Layer 2 ----
    k_prep<<<20, 256>>>(W2, as2, ad2);
    k_escore<<<gw, 256>>>(d_X_ptr);
    k_alpha<<<gw, 256>>>();
    k_gather<<<gw, 256>>>(d_X_ptr);
    k_gemm_tc<<<gm, 256>>>(b2, g2, bb2, nullptr, 0);

    // ---- Layer 3 ----
    k_prep<<<20, 256>>>(W3, as3, ad3);
    k_escore<<<gw, 256>>>(d_X_ptr);
    k_alpha<<<gw, 256>>>();
    k_gather<<<gw, 256>>>(d_X_ptr);
    k_gemm_tc<<<gm, 256>>>(b3, nullptr, nullptr, out, 1);
}